// round 17
// baseline (speedup 1.0000x reference)
#include <cuda_runtime.h>
#include <cuda_bf16.h>
#include <cstdint>

#define KC      128
#define NPIX    (16 * 8192)
#define NTILES  2048            // 64 px per tile
#define KPB     272             // bf16 image row stride bytes (128 k + pad), 16B-mult
#define KP      136             // elems
#define PART    17408           // bytes per part of one tile image (64*272)
#define TILEB   52224           // 3*PART  : split3 tile bytes
#define RPITCH  66              // r fp32 row stride (elems)
#define RTILEB  33792           // 128*66*4 : r tile bytes
#define WA_B    104448          // 3*128*272 : one stage's weight image bytes

typedef unsigned long long ull;

// ---- device-global intermediates (static allocs are legal) ----
__device__ __nv_bfloat16 g_WimgF[4][3 * 128 * KP];       // [s][part][o][k]
__device__ float         g_bias[4][KC];
__device__ __align__(16) char  g_Xs [(size_t)NTILES * TILEB];   // x  split3 tiles
__device__ __align__(16) char  g_Hs [(size_t)NTILES * TILEB];   // h  split3 tiles
__device__ __align__(16) char  g_X2s[(size_t)NTILES * TILEB];   // x2 split3 tiles
__device__ __align__(16) float g_Rf [(size_t)NTILES * 128 * RPITCH]; // r fp32 tiles
__device__ int           g_ind[NPIX];

__device__ __forceinline__ float lrelu_f(float x) { return x >= 0.0f ? x : 0.01f * x; }
__device__ __forceinline__ uint32_t smem_u32(const void* p) {
    uint32_t a; asm("{ .reg .u64 t; cvta.to.shared.u64 t, %1; cvt.u32.u64 %0, t; }" : "=r"(a) : "l"(p));
    return a;
}
__device__ __forceinline__ void ldsm4(uint32_t a, uint32_t* r) {
    asm volatile("ldmatrix.sync.aligned.m8n8.x4.shared.b16 {%0,%1,%2,%3}, [%4];"
                 : "=r"(r[0]), "=r"(r[1]), "=r"(r[2]), "=r"(r[3]) : "r"(a));
}
__device__ __forceinline__ void mma_bf16(float* c, const uint32_t* a, uint32_t b0, uint32_t b1) {
    asm volatile("mma.sync.aligned.m16n8k16.row.col.f32.bf16.bf16.f32 "
                 "{%0,%1,%2,%3}, {%4,%5,%6,%7}, {%8,%9}, {%0,%1,%2,%3};"
                 : "+f"(c[0]), "+f"(c[1]), "+f"(c[2]), "+f"(c[3])
                 : "r"(a[0]), "r"(a[1]), "r"(a[2]), "r"(a[3]), "r"(b0), "r"(b1));
}
#define CP_ASYNC16(dst, src) \
    asm volatile("cp.async.cg.shared.global [%0], [%1], 16;" :: "r"(dst), "l"(src) : "memory")
#define CP_COMMIT()  asm volatile("cp.async.commit_group;" ::: "memory")
#define CP_WAIT(n)   asm volatile("cp.async.wait_group %0;" :: "n"(n) : "memory")

__device__ __forceinline__ void split3(float v, __nv_bfloat16& h1, __nv_bfloat16& h2, __nv_bfloat16& h3) {
    h1 = __float2bfloat16(v);
    float r1 = v - __bfloat162float(h1);
    h2 = __float2bfloat16(r1);
    h3 = __float2bfloat16(r1 - __bfloat162float(h2));
}
__device__ __forceinline__ void store_split3_s(char* b, int px, int o, float v) {
    __nv_bfloat16 h1, h2, h3; split3(v, h1, h2, h3);
    *(__nv_bfloat16*)(b + px * KPB + o * 2)            = h1;
    *(__nv_bfloat16*)(b + PART + px * KPB + o * 2)     = h2;
    *(__nv_bfloat16*)(b + 2 * PART + px * KPB + o * 2) = h3;
}
__device__ __forceinline__ float rd3(const char* b, int px, int k) {
    return __bfloat162float(*(const __nv_bfloat16*)(b + px * KPB + k * 2))
         + __bfloat162float(*(const __nv_bfloat16*)(b + PART + px * KPB + k * 2))
         + __bfloat162float(*(const __nv_bfloat16*)(b + 2 * PART + px * KPB + k * 2));
}
__device__ __forceinline__ ull packdup(float x) { ull r; asm("mov.b64 %0, {%1,%1};" : "=l"(r) : "f"(x)); return r; }
__device__ __forceinline__ ull ffma2(ull a, ull b, ull c) { ull d; asm("fma.rn.f32x2 %0, %1, %2, %3;" : "=l"(d) : "l"(a), "l"(b), "l"(c)); return d; }
__device__ __forceinline__ float2 unpack2(ull v) { float2 f; asm("mov.b64 {%0,%1}, %2;" : "=f"(f.x), "=f"(f.y) : "l"(v)); return f; }

// ================= prep: BN-fold + bf16 3-split weights, [part][o][k] =====================
__global__ void prep_kernel(const float* __restrict__ cl1_w, const float* __restrict__ cl1_b,
                            const float* __restrict__ cl1_g, const float* __restrict__ cl1_bt,
                            const float* __restrict__ cl1_m, const float* __restrict__ cl1_v,
                            const float* __restrict__ cl2_w, const float* __restrict__ cl2_b,
                            const float* __restrict__ cl3_w, const float* __restrict__ cl3_b,
                            const float* __restrict__ reg1_w, const float* __restrict__ reg1_b,
                            const float* __restrict__ reg1_g, const float* __restrict__ reg1_bt,
                            const float* __restrict__ reg1_m, const float* __restrict__ reg1_v)
{
    int t = blockIdx.x * blockDim.x + threadIdx.x;
    if (t < 4 * KC * KC) {
        int s = t >> 14, idx = t & 16383, o = idx >> 7, k = idx & 127;
        const float* W = (s == 0) ? cl1_w : (s == 1) ? reg1_w : (s == 2) ? cl2_w : cl3_w;
        float sc = 1.0f;
        if (s == 0)      sc = cl1_g[o]  * rsqrtf(cl1_v[o]  + 1e-5f);
        else if (s == 1) sc = reg1_g[o] * rsqrtf(reg1_v[o] + 1e-5f);
        float v = W[o * KC + k] * sc;
        __nv_bfloat16 h1, h2, h3; split3(v, h1, h2, h3);
        int base = o * KP + k;
        g_WimgF[s][base]                = h1;
        g_WimgF[s][128 * KP + base]     = h2;
        g_WimgF[s][2 * 128 * KP + base] = h3;
    }
    if (t < 4 * KC) {
        int s = t >> 7, o = t & 127;
        float b;
        if (s == 0)      b = (cl1_b[o]  - cl1_m[o])  * (cl1_g[o]  * rsqrtf(cl1_v[o]  + 1e-5f)) + cl1_bt[o];
        else if (s == 1) b = (reg1_b[o] - reg1_m[o]) * (reg1_g[o] * rsqrtf(reg1_v[o] + 1e-5f)) + reg1_bt[o];
        else if (s == 2) b = cl2_b[o];
        else             b = cl3_b[o];
        g_bias[s][o] = b;
    }
}

// ================= split_x: x_in -> g_Xs split3 tiles =====================================
__global__ __launch_bounds__(256, 4)
void split_x_kernel(const float* __restrict__ x_in)
{
    int t   = blockIdx.x;
    int px  = threadIdx.x & 63;
    int c0  = (threadIdx.x >> 6) * 32;
    int bb  = t >> 7;
    int w0  = (t & 127) * 64;
    char* dst = g_Xs + (size_t)t * TILEB;
    __nv_bfloat16 p1[32], p2[32], p3[32];
#pragma unroll 8
    for (int cc = 0; cc < 32; cc++) {
        float v = x_in[((size_t)bb * KC + c0 + cc) * 8192 + w0 + px];
        split3(v, p1[cc], p2[cc], p3[cc]);
    }
    char* r1 = dst + px * KPB + c0 * 2;
#pragma unroll
    for (int q = 0; q < 4; q++) {
        *(uint4*)(r1 + q * 16)            = *(uint4*)&p1[q * 8];
        *(uint4*)(r1 + PART + q * 16)     = *(uint4*)&p2[q * 8];
        *(uint4*)(r1 + 2 * PART + q * 16) = *(uint4*)&p3[q * 8];
    }
}

// ================= weight-stationary GEMM (4 launches: s=0 cl1, 1 reg1, 2 cl2, 3 cl3) =====
// dyn smem: WA [0,104448) | B0 [104448,156672) | B1 [156672,208896)
#define GB0 104448
#define GSMEM 208896

__global__ __launch_bounds__(512, 1)
void gemm_stage_kernel(int s, const float* __restrict__ cl3_w, const float* __restrict__ cl3_b,
                       float* __restrict__ out)
{
    extern __shared__ __align__(16) char smc[];
    const uint32_t smb = smem_u32(smc);

    __shared__ float sbias[KC];
    __shared__ float redv[8][64];
    __shared__ int   redi[8][64];
    __shared__ float s_msk[64][8];

    const int tid  = threadIdx.x;
    const int wid  = tid >> 5;
    const int lane = tid & 31;
    const int og   = wid >> 1;
    const int ph   = wid & 1;
    const int g    = lane >> 2;
    const int tig  = lane & 3;

    if (tid < KC) sbias[tid] = g_bias[s][tid];

    const char* Bimg = (s <= 1) ? g_Xs : (s == 2) ? g_Hs : g_X2s;
    char*  Dsplit = (s == 0) ? g_Hs : g_X2s;     // used for s=0,2
    float* Dr     = g_Rf;                        // used for s=1

    // ---- load full weight image (3 parts x 128 x 272B) via cp.async ----
    {
        const char* src = (const char*)(&g_WimgF[s][0]);
        for (int i = tid; i < WA_B / 16; i += 512)
            CP_ASYNC16(smb + i * 16, src + i * 16);
        CP_COMMIT();
    }

    // ldmatrix lane offsets (validated plumbing, full-row strides)
    const int mId = lane >> 3;
    const uint32_t aLane = (uint32_t)((og * 16 + (mId & 1) * 8 + (lane & 7)) * KPB + (mId >> 1) * 16);
    uint32_t bLane[2];
#pragma unroll
    for (int nt = 0; nt < 2; nt++)
        bLane[nt] = (uint32_t)((ph * 32 + nt * 16 + (mId >> 1) * 8 + (lane & 7)) * KPB + (mId & 1) * 16);

    // ---- preload first tile into B0 ----
    int t0 = blockIdx.x;
    if (t0 < NTILES) {
        const char* src = Bimg + (size_t)t0 * TILEB;
        for (int i = tid; i < TILEB / 16; i += 512)
            CP_ASYNC16(smb + GB0 + i * 16, src + i * 16);
    }
    CP_COMMIT();

    int cur = 0;
    float acc[4][4];

    for (int t = t0; t < NTILES; t += 148) {
        int tn = t + 148;
        bool pre = (tn < NTILES);
        if (pre) {   // preload next tile into other buffer
            const char* src = Bimg + (size_t)tn * TILEB;
            uint32_t db = smb + GB0 + (cur ^ 1) * TILEB;
            for (int i = tid; i < TILEB / 16; i += 512)
                CP_ASYNC16(db + i * 16, src + i * 16);
            CP_COMMIT();
            CP_WAIT(1);
        } else {
            CP_WAIT(0);
        }
        __syncthreads();                          // B[cur] (and WA) visible to all

        const uint32_t bBase = smb + GB0 + cur * TILEB;
#pragma unroll
        for (int j = 0; j < 4; j++)
#pragma unroll
            for (int e = 0; e < 4; e++) acc[j][e] = 0.0f;

#pragma unroll 2
        for (int ks = 0; ks < 8; ks++) {
            uint32_t a1[4], a2[4], a3[4];
            uint32_t ka = smb + aLane + ks * 32;
            ldsm4(ka,             a1);
            ldsm4(ka + 34816,     a2);
            ldsm4(ka + 69632,     a3);
#pragma unroll
            for (int nt = 0; nt < 2; nt++) {
                uint32_t b1[4], b2[4], b3[4];
                uint32_t kb = bBase + bLane[nt] + ks * 32;
                ldsm4(kb,            b1);
                ldsm4(kb + PART,     b2);
                ldsm4(kb + 2 * PART, b3);
                float* cl = acc[nt * 2];
                float* ch = acc[nt * 2 + 1];
                mma_bf16(cl, a1, b1[0], b1[1]);
                mma_bf16(cl, a1, b2[0], b2[1]);
                mma_bf16(cl, a2, b1[0], b1[1]);
                mma_bf16(cl, a2, b2[0], b2[1]);
                mma_bf16(cl, a1, b3[0], b3[1]);
                mma_bf16(cl, a3, b1[0], b1[1]);
                mma_bf16(ch, a1, b1[2], b1[3]);
                mma_bf16(ch, a1, b2[2], b2[3]);
                mma_bf16(ch, a2, b1[2], b1[3]);
                mma_bf16(ch, a2, b2[2], b2[3]);
                mma_bf16(ch, a1, b3[2], b3[3]);
                mma_bf16(ch, a3, b1[2], b1[3]);
            }
        }

        const int oA = og * 16 + g, oB = oA + 8;

        if (s == 3) {
            // ---------- argmax + mask (no gmem D) ----------
            float bA = sbias[oA], bB = sbias[oB];
            float bv[8]; int bi[8];
#pragma unroll
            for (int j = 0; j < 4; j++) {
#pragma unroll
                for (int e = 0; e < 2; e++) {
                    float vA = acc[j][e] + bA;
                    float vB = acc[j][2 + e] + bB;
                    bv[j * 2 + e] = (vB > vA) ? vB : vA;       // tie keeps oA (smaller)
                    bi[j * 2 + e] = (vB > vA) ? oB : oA;
                }
            }
#pragma unroll
            for (int st = 4; st <= 16; st <<= 1) {             // butterfly over g (lane bits 2..4)
#pragma unroll
                for (int j = 0; j < 8; j++) {
                    float ov = __shfl_xor_sync(0xFFFFFFFFu, bv[j], st);
                    int   oi = __shfl_xor_sync(0xFFFFFFFFu, bi[j], st);
                    if (ov > bv[j] || (ov == bv[j] && oi < bi[j])) { bv[j] = ov; bi[j] = oi; }
                }
            }
            if (lane < 4) {
#pragma unroll
                for (int j = 0; j < 8; j++) {
                    int px = ph * 32 + (j >> 1) * 8 + lane * 2 + (j & 1);
                    redv[og][px] = bv[j];
                    redi[og][px] = bi[j];
                }
            }
            // mask partials: thread (p, q) handles k in [q*16, q*16+16)
            {
                int q = tid >> 6, p = tid & 63;
                const char* bx = (const char*)smc + GB0 + cur * TILEB;
                const float* mrow = cl3_w + 128 * KC;
                float part = 0.0f;
#pragma unroll 4
                for (int kk = 0; kk < 16; kk++) {
                    int k = q * 16 + kk;
                    part = fmaf(__ldg(mrow + k), rd3(bx, p, k), part);
                }
                s_msk[p][q] = part;
            }
            __syncthreads();
            if (tid < 64) {
                int p = tid;
                float mv = redv[0][p]; int mi = redi[0][p];
#pragma unroll
                for (int w = 1; w < 8; w++) {                  // ascending og == ascending o
                    float v = redv[w][p]; int ii = redi[w][p];
                    if (v > mv || (v == mv && ii < mi)) { mv = v; mi = ii; }
                }
                int gp0 = t * 64;
                g_ind[gp0 + p] = mi;
                float macc = __ldg(cl3_b + 128);
#pragma unroll
                for (int q = 0; q < 8; q++) macc += s_msk[p][q];
                out[NPIX + gp0 + p] = lrelu_f(macc);
            }
            __syncthreads();                                   // protect B[cur] until done
        } else {
            // ---------- epilogue into B[cur] (consumed), then flat copy out ----------
            __syncthreads();                                   // everyone done ldsm-ing B[cur]
            char* bc = (char*)smc + GB0 + cur * TILEB;
            float bA = sbias[oA], bB = sbias[oB];
            if (s == 1) {
                float* rf = (float*)bc;
#pragma unroll
                for (int j = 0; j < 4; j++) {
                    int px = ph * 32 + j * 8 + tig * 2;
                    rf[oA * RPITCH + px]     = lrelu_f(acc[j][0] + bA);
                    rf[oA * RPITCH + px + 1] = lrelu_f(acc[j][1] + bA);
                    rf[oB * RPITCH + px]     = lrelu_f(acc[j][2] + bB);
                    rf[oB * RPITCH + px + 1] = lrelu_f(acc[j][3] + bB);
                }
            } else {
#pragma unroll
                for (int j = 0; j < 4; j++) {
                    int px = ph * 32 + j * 8 + tig * 2;
                    store_split3_s(bc, px,     oA, lrelu_f(acc[j][0] + bA));
                    store_split3_s(bc, px + 1, oA, lrelu_f(acc[j][1] + bA));
                    store_split3_s(bc, px,     oB, lrelu_f(acc[j][2] + bB));
                    store_split3_s(bc, px + 1, oB, lrelu_f(acc[j][3] + bB));
                }
            }
            __syncthreads();
            int nb = (s == 1) ? RTILEB / 16 : TILEB / 16;
            char* gdst = (s == 1) ? (char*)(Dr + (size_t)t * 128 * RPITCH)
                                  : Dsplit + (size_t)t * TILEB;
            const uint4* sp4 = (const uint4*)bc;
            uint4* dp4 = (uint4*)gdst;
            for (int i = tid; i < nb; i += 512) dp4[i] = sp4[i];
            __syncthreads();                                   // all LDS of B[cur] done before refill
        }
        cur ^= 1;
    }
}

// ================= stage5: y = lrelu(cat[r;h] @ w2[sp]) ; out = (ind + y.w3)/128 ==========
// dyn smem: HS split3 [0,52224) | Rf [52224,86016) | Hf [86016,118784)
#define S5_RF 52224
#define S5_HF 86016
#define S5_SMEM 118784

__global__ __launch_bounds__(512, 1)
void stage5_kernel(const float* __restrict__ w2, const float* __restrict__ b2,
                   const float* __restrict__ w3, const float* __restrict__ b3,
                   float* __restrict__ out)
{
    extern __shared__ __align__(16) char smc[];
    __shared__ float s_pred[64][8];

    const int tid = threadIdx.x;
    const int t   = blockIdx.x;
    const int gp0 = t * 64;

    // flat load h split3 + r fp32 tiles
    {
        const uint4* hs = (const uint4*)(g_Hs + (size_t)t * TILEB);
        uint4* d0 = (uint4*)smc;
        for (int i = tid; i < TILEB / 16; i += 512) d0[i] = hs[i];
        const uint4* rs = (const uint4*)(g_Rf + (size_t)t * 128 * RPITCH);
        uint4* d1 = (uint4*)(smc + S5_RF);
        for (int i = tid; i < RTILEB / 16; i += 512) d1[i] = rs[i];
    }
    __syncthreads();
    // reconstruct Hf [128][64] fp32
    {
        float* Hf = (float*)(smc + S5_HF);
#pragma unroll
        for (int rep = 0; rep < 4; rep++) {
            int slot = tid + rep * 512;          // 2048 slots x 4 c each
            int px = slot & 63, c4 = slot >> 6;
            ull v1 = *(const ull*)(smc + px * KPB + c4 * 8);
            ull v2 = *(const ull*)(smc + PART + px * KPB + c4 * 8);
            ull v3 = *(const ull*)(smc + 2 * PART + px * KPB + c4 * 8);
#pragma unroll
            for (int e = 0; e < 4; e++) {
                uint16_t u1 = (uint16_t)(v1 >> (16 * e));
                uint16_t u2 = (uint16_t)(v2 >> (16 * e));
                uint16_t u3 = (uint16_t)(v3 >> (16 * e));
                Hf[(c4 * 4 + e) * 64 + px] =
                    __bfloat162float(*(__nv_bfloat16*)&u1) +
                    __bfloat162float(*(__nv_bfloat16*)&u2) +
                    __bfloat162float(*(__nv_bfloat16*)&u3);
            }
        }
    }
    __syncthreads();

    {
        int q = tid >> 6;                 // 0..7 -> outputs q*4..q*4+4
        int p = tid & 63;
        int ind = g_ind[gp0 + p];
        int sp  = ind >> 4;
        const float* Rf = (const float*)(smc + S5_RF);
        const float* Hf = (const float*)(smc + S5_HF);
        const float* wp = w2 + (size_t)sp * (256 * 32) + q * 4;
        const ulonglong2* binit = (const ulonglong2*)(b2 + sp * 32 + q * 4);
        ulonglong2 t0 = binit[0];
        ull y[2] = { t0.x, t0.y };
#pragma unroll 4
        for (int f = 0; f < 128; f++) {
            ull c = packdup(Rf[f * RPITCH + p]);
            const ulonglong2* wq = (const ulonglong2*)(wp + f * 32);
            ulonglong2 u0 = wq[0];
            y[0] = ffma2(c, u0.x, y[0]); y[1] = ffma2(c, u0.y, y[1]);
        }
#pragma unroll 4
        for (int f = 0; f < 128; f++) {
            ull c = packdup(Hf[f * 64 + p]);
            const ulonglong2* wq = (const ulonglong2*)(wp + (128 + f) * 32);
            ulonglong2 u0 = wq[0];
            y[0] = ffma2(c, u0.x, y[0]); y[1] = ffma2(c, u0.y, y[1]);
        }
        const float* w3p = w3 + ind * 32 + q * 4;
        float part = 0.0f;
#pragma unroll
        for (int r = 0; r < 2; r++) {
            float2 v = unpack2(y[r]);
            part = fmaf(lrelu_f(v.x), __ldg(w3p + 2 * r),     part);
            part = fmaf(lrelu_f(v.y), __ldg(w3p + 2 * r + 1), part);
        }
        s_pred[p][q] = part;
    }
    __syncthreads();
    if (tid < 64) {
        int p = tid;
        int ind = g_ind[gp0 + p];
        float reg = s_pred[p][0] + s_pred[p][1] + s_pred[p][2] + s_pred[p][3]
                  + s_pred[p][4] + s_pred[p][5] + s_pred[p][6] + s_pred[p][7]
                  + __ldg(b3 + ind);
        out[gp0 + p] = ((float)ind + reg) * 0.0078125f;
    }
}

extern "C" void kernel_launch(void* const* d_in, const int* in_sizes, int n_in,
                              void* d_out, int out_size) {
    if (n_in < 21 || d_out == nullptr) return;

    const float* x_in    = (const float*)d_in[0];
    const float* cl1_w   = (const float*)d_in[1];
    const float* cl1_b   = (const float*)d_in[2];
    const float* cl1_g   = (const float*)d_in[3];
    const float* cl1_bt  = (const float*)d_in[4];
    const float* cl1_m   = (const float*)d_in[5];
    const float* cl1_v   = (const float*)d_in[6];
    const float* cl2_w   = (const float*)d_in[7];
    const float* cl2_b   = (const float*)d_in[8];
    const float* cl3_w   = (const float*)d_in[9];
    const float* cl3_b   = (const float*)d_in[10];
    const float* reg1_w  = (const float*)d_in[11];
    const float* reg1_b  = (const float*)d_in[12];
    const float* reg1_g  = (const float*)d_in[13];
    const float* reg1_bt = (const float*)d_in[14];
    const float* reg1_m  = (const float*)d_in[15];
    const float* reg1_v  = (const float*)d_in[16];
    const float* w2      = (const float*)d_in[17];
    const float* b2      = (const float*)d_in[18];
    const float* w3      = (const float*)d_in[19];
    const float* b3      = (const float*)d_in[20];
    float* out = (float*)d_out;

    prep_kernel<<<(4 * 128 * 128 + 255) / 256, 256>>>(
        cl1_w, cl1_b, cl1_g, cl1_bt, cl1_m, cl1_v,
        cl2_w, cl2_b, cl3_w, cl3_b,
        reg1_w, reg1_b, reg1_g, reg1_bt, reg1_m, reg1_v);

    split_x_kernel<<<NTILES, 256>>>(x_in);

    cudaFuncSetAttribute(gemm_stage_kernel,
                         cudaFuncAttributeMaxDynamicSharedMemorySize, GSMEM);
    gemm_stage_kernel<<<148, 512, GSMEM>>>(0, cl3_w, cl3_b, out);   // cl1 : x  -> h
    gemm_stage_kernel<<<148, 512, GSMEM>>>(1, cl3_w, cl3_b, out);   // reg1: x  -> r
    gemm_stage_kernel<<<148, 512, GSMEM>>>(2, cl3_w, cl3_b, out);   // cl2 : h  -> x2
    gemm_stage_kernel<<<148, 512, GSMEM>>>(3, cl3_w, cl3_b, out);   // cl3 : x2 -> ind, mask

    cudaFuncSetAttribute(stage5_kernel,
                         cudaFuncAttributeMaxDynamicSharedMemorySize, S5_SMEM);
    stage5_kernel<<<NTILES, 512, S5_SMEM>>>(w2, b2, w3, b3, out);
}